// round 14
// baseline (speedup 1.0000x reference)
#include <cuda_runtime.h>
#include <cuda_bf16.h>
#include <cstdint>

#define BATCH    1024
#define TOT      4096
#define SEN      1024
#define CNNOUT   3264
#define KPAD     3328
#define NOUT     1968
#define NOUT_PAD 2048

// ---------------- scratch device globals (no allocations) -------------------
__device__ __align__(256) __nv_bfloat16 g_featH[(size_t)BATCH * KPAD];
__device__ __align__(256) __nv_bfloat16 g_featL[(size_t)BATCH * KPAD];
__device__ __align__(256) __nv_bfloat16 g_ipwH [(size_t)SEN * KPAD];
__device__ __align__(256) __nv_bfloat16 g_ipwL [(size_t)SEN * KPAD];
__device__ __align__(256) __nv_bfloat16 g_WH   [(size_t)TOT * TOT];
__device__ __align__(256) __nv_bfloat16 g_WL   [(size_t)TOT * TOT];
__device__ __align__(256) __nv_bfloat16 g_owH  [(size_t)NOUT_PAD * 1024];
__device__ __align__(256) __nv_bfloat16 g_owL  [(size_t)NOUT_PAD * 1024];
__device__ __align__(256) __nv_bfloat16 g_P0H  [(size_t)BATCH * TOT];
__device__ __align__(256) __nv_bfloat16 g_P0L  [(size_t)BATCH * TOT];
__device__ __align__(256) __nv_bfloat16 g_P1H  [(size_t)BATCH * TOT];
__device__ __align__(256) __nv_bfloat16 g_P1L  [(size_t)BATCH * TOT];
__device__ __align__(256) __nv_bfloat16 g_OPH  [(size_t)BATCH * 1024];
__device__ __align__(256) __nv_bfloat16 g_OPL  [(size_t)BATCH * 1024];
__device__ __align__(256) __nv_bfloat16 g_laH [(size_t)TOT * 64];
__device__ __align__(256) __nv_bfloat16 g_laL [(size_t)TOT * 64];
__device__ __align__(256) __nv_bfloat16 g_lbtH[(size_t)TOT * 64];
__device__ __align__(256) __nv_bfloat16 g_lbtL[(size_t)TOT * 64];
__device__ __align__(256) float g_part[(size_t)4 * BATCH * 1024];   // split-K partials (16MB)

// ---------------- helpers ----------------------------------------------------
__device__ __forceinline__ uint32_t smem_u32(const void* p) {
    uint32_t a;
    asm("{ .reg .u64 t; cvta.to.shared.u64 t, %1; cvt.u32.u64 %0, t; }" : "=r"(a) : "l"(p));
    return a;
}
__device__ __forceinline__ void cpa(uint32_t dst, const void* src) {
    asm volatile("cp.async.cg.shared.global [%0], [%1], 16;" :: "r"(dst), "l"(src));
}
#define CP_COMMIT() asm volatile("cp.async.commit_group;")
#define CP_WAIT0()  asm volatile("cp.async.wait_group 0;")
#define CP_WAIT1()  asm volatile("cp.async.wait_group 1;")

__device__ __forceinline__ void ldsm4(uint32_t* r, uint32_t addr) {
    asm volatile("ldmatrix.sync.aligned.m8n8.x4.shared.b16 {%0,%1,%2,%3}, [%4];"
                 : "=r"(r[0]), "=r"(r[1]), "=r"(r[2]), "=r"(r[3]) : "r"(addr));
}
__device__ __forceinline__ void mma16816(float* c, const uint32_t* a, const uint32_t* b) {
    asm volatile("mma.sync.aligned.m16n8k16.row.col.f32.bf16.bf16.f32 "
                 "{%0,%1,%2,%3}, {%4,%5,%6,%7}, {%8,%9}, {%0,%1,%2,%3};"
                 : "+f"(c[0]), "+f"(c[1]), "+f"(c[2]), "+f"(c[3])
                 : "r"(a[0]), "r"(a[1]), "r"(a[2]), "r"(a[3]), "r"(b[0]), "r"(b[1]));
}

__device__ __forceinline__ void split8(const float* v, uint4& uh, uint4& ul) {
    uint32_t h[4], l[4];
#pragma unroll
    for (int q = 0; q < 4; q++) {
        __nv_bfloat16 b0 = __float2bfloat16(v[2 * q]);
        __nv_bfloat16 b1 = __float2bfloat16(v[2 * q + 1]);
        float r0 = v[2 * q]     - __bfloat162float(b0);
        float r1 = v[2 * q + 1] - __bfloat162float(b1);
        __nv_bfloat16 c0 = __float2bfloat16(r0);
        __nv_bfloat16 c1 = __float2bfloat16(r1);
        h[q] = (uint32_t)__bfloat16_as_ushort(b0) | ((uint32_t)__bfloat16_as_ushort(b1) << 16);
        l[q] = (uint32_t)__bfloat16_as_ushort(c0) | ((uint32_t)__bfloat16_as_ushort(c1) << 16);
    }
    uh = make_uint4(h[0], h[1], h[2], h[3]);
    ul = make_uint4(l[0], l[1], l[2], l[3]);
}
__device__ __forceinline__ void pack2(float v0, float v1, uint32_t& ph, uint32_t& pl) {
    __nv_bfloat16 h0 = __float2bfloat16(v0);
    __nv_bfloat16 h1 = __float2bfloat16(v1);
    __nv_bfloat16 q0 = __float2bfloat16(v0 - __bfloat162float(h0));
    __nv_bfloat16 q1 = __float2bfloat16(v1 - __bfloat162float(h1));
    ph = (uint32_t)__bfloat16_as_ushort(h0) | ((uint32_t)__bfloat16_as_ushort(h1) << 16);
    pl = (uint32_t)__bfloat16_as_ushort(q0) | ((uint32_t)__bfloat16_as_ushort(q1) << 16);
}
__device__ __forceinline__ float bflo(uint32_t u) {
    return __bfloat162float(__ushort_as_bfloat16((unsigned short)(u & 0xFFFF)));
}
__device__ __forceinline__ float bfhi(uint32_t u) {
    return __bfloat162float(__ushort_as_bfloat16((unsigned short)(u >> 16)));
}

struct ConvPtrs { const float* w[8]; };

// ---------------- fused: conv feature extraction + ip_w pack ----------------
__global__ __launch_bounds__(256) void fused_prep(
    const float* __restrict__ x, ConvPtrs cw, const float* __restrict__ conv_b,
    __nv_bfloat16* __restrict__ fH, __nv_bfloat16* __restrict__ fL,
    const float* __restrict__ ipw,
    __nv_bfloat16* __restrict__ iH, __nv_bfloat16* __restrict__ iL)
{
    __shared__ float sm[64 * 65];
    const int tid = threadIdx.x;
    const int bid = blockIdx.x;

    if (bid < BATCH) {
        float* xs = sm;
        const float* xb = x + bid * 512;
        for (int i = tid; i < 512; i += 256) xs[i] = xb[i];
        __syncthreads();

        const int offs[9] = {0, 1024, 1808, 2384, 2784, 3040, 3184, 3248, 3264};
        for (int o = tid; o < KPAD; o += 256) {
            if (o >= CNNOUT) {
                fH[(size_t)bid * KPAD + o] = __ushort_as_bfloat16(0);
                fL[(size_t)bid * KPAD + o] = __ushort_as_bfloat16(0);
                continue;
            }
            int k = 1;
            while (o >= offs[k]) k++;
            int local = o - offs[k - 1];
            int H = 9 - k;
            int f = local / (H * H);
            int rem = local - f * H * H;
            int i0 = rem / H;
            int j0 = rem - i0 * H;

            const float* w = cw.w[k - 1] + f * 8 * k * k;
            float acc = conv_b[(k - 1) * 16 + f];
            for (int c = 0; c < 8; c++) {
                const float* wc = w + c * k * k;
                for (int p = 0; p < k; p++)
                    for (int q = 0; q < k; q++)
                        acc += xs[((i0 + p) * 8 + (j0 + q)) * 8 + c] * wc[p * k + q];
            }
            float e = fmaxf(acc, 0.0f);
            __nv_bfloat16 bh = __float2bfloat16(e);
            __nv_bfloat16 bl = __float2bfloat16(e - __bfloat162float(bh));
            fH[(size_t)bid * KPAD + o] = bh;
            fL[(size_t)bid * KPAD + o] = bl;
        }
    } else {
        const int pb = bid - BATCH;
        const int k0 = (pb % (KPAD / 64)) * 64;
        const int n0 = (pb / (KPAD / 64)) * 64;

        for (int i = tid; i < 4096; i += 256) {
            int k = i >> 6, n = i & 63;
            int gn = n0 + n, gk = k0 + k;
            sm[k * 65 + n] = (gn < SEN && gk < CNNOUT) ? ipw[(size_t)gk * SEN + gn] : 0.0f;
        }
        __syncthreads();

        for (int it = tid; it < 512; it += 256) {
            int n = it & 63, kg = it >> 6;
            float v[8];
#pragma unroll
            for (int j = 0; j < 8; j++) v[j] = sm[(kg * 8 + j) * 65 + n];
            uint4 uh, ul;
            split8(v, uh, ul);
            size_t o = (size_t)(n0 + n) * KPAD + k0 + kg * 8;
            *(uint4*)((char*)iH + o * 2) = uh;
            *(uint4*)((char*)iL + o * 2) = ul;
        }
    }
}

// ---------------- pack [K,N] fp32 weight transposed -> [N,K] hi/lo bf16 -----
__global__ __launch_bounds__(256) void pack_wT(const float* __restrict__ w,
                                               int ldw, int ntrue, int ktrue, int ldk,
                                               __nv_bfloat16* __restrict__ H,
                                               __nv_bfloat16* __restrict__ L)
{
    __shared__ float sm[64 * 65];
    const int k0 = blockIdx.x * 64, n0 = blockIdx.y * 64;
    const int tid = threadIdx.x;

    for (int i = tid; i < 4096; i += 256) {
        int k = i >> 6, n = i & 63;
        int gn = n0 + n, gk = k0 + k;
        sm[k * 65 + n] = (gn < ntrue && gk < ktrue) ? w[(size_t)gk * ldw + gn] : 0.0f;
    }
    __syncthreads();

    for (int it = tid; it < 512; it += 256) {
        int n = it & 63, kg = it >> 6;
        float v[8];
#pragma unroll
        for (int j = 0; j < 8; j++) v[j] = sm[(kg * 8 + j) * 65 + n];
        uint4 uh, ul;
        split8(v, uh, ul);
        size_t o = (size_t)(n0 + n) * ldk + k0 + kg * 8;
        *(uint4*)((char*)H + o * 2) = uh;
        *(uint4*)((char*)L + o * 2) = ul;
    }
}

// ---------------- straight split-copy fp32 -> hi/lo bf16 --------------------
__global__ void split_copy(const float* __restrict__ in,
                           __nv_bfloat16* __restrict__ H,
                           __nv_bfloat16* __restrict__ L, int n8)
{
    int i = blockIdx.x * blockDim.x + threadIdx.x;
    if (i >= n8) return;
    float v[8];
    *(float4*)(v)     = *(const float4*)(in + (size_t)i * 8);
    *(float4*)(v + 4) = *(const float4*)(in + (size_t)i * 8 + 4);
    uint4 uh, ul;
    split8(v, uh, ul);
    *(uint4*)((char*)H + (size_t)i * 16) = uh;
    *(uint4*)((char*)L + (size_t)i * 16) = ul;
}

// ---------------- generic split-K reduce epilogue ---------------------------
__global__ __launch_bounds__(256) void epi_reduce(
    const float* __restrict__ part, int nz, int partW2,
    const float* __restrict__ bias,
    const __nv_bfloat16* __restrict__ addH, const __nv_bfloat16* __restrict__ addL,
    int ld_add, int do_relu,
    float* __restrict__ fOut, int ldO, int ncolO,
    __nv_bfloat16* __restrict__ PH, __nv_bfloat16* __restrict__ PL, int ldP)
{
    const int i = blockIdx.x * blockDim.x + threadIdx.x;
    const int r = i / partW2;
    const int c2 = (i - r * partW2) * 2;
    const int partW = partW2 * 2;
    if (r >= BATCH) return;
    float v0 = 0.0f, v1 = 0.0f;
    for (int z = 0; z < nz; z++) {
        float2 p = *(const float2*)(part + (size_t)z * BATCH * partW + (size_t)r * partW + c2);
        v0 += p.x; v1 += p.y;
    }
    if (bias && c2 + 1 < ncolO) {
        float2 b = *(const float2*)(bias + c2);
        v0 += b.x; v1 += b.y;
    }
    if (addH) {
        uint32_t uh = *(const uint32_t*)((const char*)addH + ((size_t)r * ld_add + c2) * 2);
        uint32_t ul = *(const uint32_t*)((const char*)addL + ((size_t)r * ld_add + c2) * 2);
        v0 += bflo(uh) + bflo(ul);
        v1 += bfhi(uh) + bfhi(ul);
    }
    if (do_relu) { v0 = fmaxf(v0, 0.0f); v1 = fmaxf(v1, 0.0f); }
    if (fOut && c2 + 1 < ncolO)
        *(float2*)(fOut + (size_t)r * ldO + c2) = make_float2(v0, v1);
    if (PH) {
        uint32_t ph, pl;
        pack2(v0, v1, ph, pl);
        *(uint32_t*)((char*)PH + ((size_t)r * ldP + c2) * 2) = ph;
        *(uint32_t*)((char*)PL + ((size_t)r * ldP + c2) * 2) = pl;
    }
}

// ---------------- mma.sync bf16-split GEMM ----------------------------------
// 256 threads, 2 CTAs/SM (launch_bounds cap 128 regs). Tile 128x128,
// warp tile 64x32 (2Mx4N warps). KCH=32 chunks, 3 stages x 32KB = 96KB smem.
// ONE barrier per chunk. Fine-grained interleave: B(kk0) prefetch -> mt0 MMAs
// -> B(kk1) prefetch -> mt1..3 MMAs -> cpa burst -> slice 1 MMAs.
// 3-term bf16 split (drop lo*lo). blockIdx.z = split-K slice.
// MSWAP: blockIdx.x = m-tile, blockIdx.y = n-tile. WEFF: lora+mask epilogue.
template<int STAGES, int KCH, bool WEFF, bool MSWAP>
__global__ __launch_bounds__(256, 2)
void mma_gemm(const __nv_bfloat16* __restrict__ AH, const __nv_bfloat16* __restrict__ AL, int lda,
              const __nv_bfloat16* __restrict__ BH, const __nv_bfloat16* __restrict__ BL, int ldb,
              int K,
              const float* __restrict__ bias,
              const __nv_bfloat16* __restrict__ addH, const __nv_bfloat16* __restrict__ addL,
              int add_cols, int ld_add, int do_relu,
              float* __restrict__ outF, int ldF, int ncolF,
              __nv_bfloat16* __restrict__ PH, __nv_bfloat16* __restrict__ PL, int ldP,
              const float* __restrict__ Wsrc, int partStride)
{
    static_assert(KCH == 32, "chunk layout assumes KCH==32 (2 kk-slices)");
    constexpr int GPC   = KCH / 8;                 // 16B granules per row
    constexpr int AHALF = 128 * KCH * 2;
    constexpr int STG   = 4 * AHALF;
    extern __shared__ __align__(128) char smc[];

    const int tid = threadIdx.x, l = tid & 31, wid = tid >> 5;
    const int nblk = MSWAP ? blockIdx.y : blockIdx.x;
    const int mblk = MSWAP ? blockIdx.x : blockIdx.y;
    const int zo = blockIdx.z;
    const int KB = K / KCH;
    const uint32_t smb = smem_u32(smc);
    const int mrow0 = mblk * 128;
    const int nrow0 = nblk * 128;

    AH += (size_t)zo * K; AL += (size_t)zo * K;
    BH += (size_t)zo * K; BL += (size_t)zo * K;
    if (outF) outF += (size_t)zo * partStride;

    auto swof = [](int r, uint32_t g) -> uint32_t {
        return (uint32_t)r * 64 + ((g ^ (uint32_t)((r >> 1) & 3)) << 4);
    };

    auto load_chunk = [&](int s, int c) {
        const int kof = c * KCH;
        const uint32_t sb = smb + (uint32_t)s * STG;
#pragma unroll
        for (int it = 0; it < (4 * 128 * GPC) / 256; it++) {
            int idx = tid + it * 256;
            int mat = idx / (128 * GPC);               // 0=AH 1=AL 2=BH 3=BL
            int j = idx - mat * (128 * GPC);
            int r = j / GPC, g = j - r * GPC;
            const __nv_bfloat16* src =
                (mat == 0 ? AH : mat == 1 ? AL : mat == 2 ? BH : BL);
            const int row0 = (mat < 2) ? mrow0 : nrow0;
            const int ld   = (mat < 2) ? lda : ldb;
            cpa(sb + (uint32_t)mat * AHALF + swof(r, (uint32_t)g),
                src + (size_t)(row0 + r) * ld + kof + g * 8);
        }
    };

    const int mw = wid & 1, nw = wid >> 1;
    const int mbase = mw * 64, nbase = nw * 32;
    const int rA0 = mbase + (l & 7) + ((l >> 3) & 1) * 8;
    const int rB0 = nbase + (l & 7) + ((l >> 3) & 1) * 8;
    const int gsel = l >> 4;

    float acc[4][4][4];
#pragma unroll
    for (int a = 0; a < 4; a++)
#pragma unroll
        for (int b = 0; b < 4; b++)
#pragma unroll
            for (int c = 0; c < 4; c++) acc[a][b][c] = 0.0f;

    // prefetch B fragments for one kk slice
    auto prefetch_B = [&](uint32_t base, int kk, uint32_t bh[4][2], uint32_t bl[4][2]) {
        const uint32_t g = 2 * kk + gsel;
#pragma unroll
        for (int p = 0; p < 2; p++) {
            uint32_t t0[4], t1[4];
            uint32_t addr = base + 2 * AHALF + swof(rB0 + p * 16, g);
            ldsm4(t0, addr);
            ldsm4(t1, addr + AHALF);
            bh[2 * p][0] = t0[0]; bh[2 * p][1] = t0[2];
            bh[2 * p + 1][0] = t0[1]; bh[2 * p + 1][1] = t0[3];
            bl[2 * p][0] = t1[0]; bl[2 * p][1] = t1[2];
            bl[2 * p + 1][0] = t1[1]; bl[2 * p + 1][1] = t1[3];
        }
    };

    // A loads + 12 MMAs for one (kk, mt) pair
    auto mma_mt = [&](uint32_t base, int kk, int mt, uint32_t bh[4][2], uint32_t bl[4][2]) {
        const uint32_t g = 2 * kk + gsel;
        uint32_t ah[4], al_[4];
        uint32_t addr = base + swof(rA0 + mt * 16, g);
        ldsm4(ah, addr);
        ldsm4(al_, addr + AHALF);
#pragma unroll
        for (int nt = 0; nt < 4; nt++) mma16816(acc[mt][nt], ah, bh[nt]);
#pragma unroll
        for (int nt = 0; nt < 4; nt++) mma16816(acc[mt][nt], ah, bl[nt]);
#pragma unroll
        for (int nt = 0; nt < 4; nt++) mma16816(acc[mt][nt], al_, bh[nt]);
    };

    // pipeline: prologue commits exactly STAGES-1 groups (empty groups are
    // in-order fences; required when KB < STAGES-1). One barrier per chunk.
#pragma unroll
    for (int s = 0; s < STAGES - 1; s++) {
        if (s < KB) load_chunk(s, s);
        CP_COMMIT();
    }
    for (int c = 0; c < KB; c++) {
        const int s = c % STAGES;
        if (STAGES == 3) { CP_WAIT1(); } else { CP_WAIT0(); }
        __syncthreads();
        const uint32_t base = smb + (uint32_t)s * STG;

        uint32_t b0h[4][2], b0l[4][2], b1h[4][2], b1l[4][2];
        prefetch_B(base, 0, b0h, b0l);
        mma_mt(base, 0, 0, b0h, b0l);          // tensor starts ASAP
        prefetch_B(base, 1, b1h, b1l);         // kk1 B loads hide under kk0 MMAs
        mma_mt(base, 0, 1, b0h, b0l);
        mma_mt(base, 0, 2, b0h, b0l);
        mma_mt(base, 0, 3, b0h, b0l);
        if (c + STAGES - 1 < KB) load_chunk((c + STAGES - 1) % STAGES, c + STAGES - 1);
        CP_COMMIT();
        mma_mt(base, 1, 0, b1h, b1l);
        mma_mt(base, 1, 1, b1h, b1l);
        mma_mt(base, 1, 2, b1h, b1l);
        mma_mt(base, 1, 3, b1h, b1l);
    }

    const int rr = l >> 2, cc = (l & 3) * 2;

    if (WEFF) {
        __syncthreads();
        float* Wt = (float*)smc;   // [n_local][kk_local], stride 129
        for (int i = tid; i < 128 * 128; i += 256) {
            int kk = i >> 7, n = i & 127;
            Wt[n * 129 + kk] = Wsrc[(size_t)(nrow0 + kk) * TOT + mrow0 + n];
        }
        __syncthreads();
#pragma unroll
        for (int mt = 0; mt < 4; mt++)
#pragma unroll
            for (int h = 0; h < 2; h++) {
                const int rl = mbase + mt * 16 + rr + h * 8;
                const size_t r = (size_t)(mrow0 + rl);
#pragma unroll
                for (int nt = 0; nt < 4; nt++) {
                    const int cl = nbase + nt * 8 + cc;
                    const int cx = nrow0 + cl;
                    float w0 = Wt[rl * 129 + cl];
                    float w1 = Wt[rl * 129 + cl + 1];
                    float v0 = (w0 == 0.0f) ? 0.0f : (w0 + 2.0f * acc[mt][nt][h * 2 + 0]);
                    float v1 = (w1 == 0.0f) ? 0.0f : (w1 + 2.0f * acc[mt][nt][h * 2 + 1]);
                    uint32_t ph, pl;
                    pack2(v0, v1, ph, pl);
                    *(uint32_t*)((char*)PH + (r * ldP + cx) * 2) = ph;
                    *(uint32_t*)((char*)PL + (r * ldP + cx) * 2) = pl;
                }
            }
        return;
    }

    const int growb = mrow0 + mbase;
    const int gcolb = nrow0 + nbase;
#pragma unroll
    for (int mt = 0; mt < 4; mt++)
#pragma unroll
        for (int h = 0; h < 2; h++) {
            const int r = growb + mt * 16 + rr + h * 8;
#pragma unroll
            for (int nt = 0; nt < 4; nt++) {
                const int cx = gcolb + nt * 8 + cc;
                float v0 = acc[mt][nt][h * 2 + 0];
                float v1 = acc[mt][nt][h * 2 + 1];
                if (bias && cx < ncolF) {
                    float2 bv = *(const float2*)(bias + cx);
                    v0 += bv.x; v1 += bv.y;
                }
                if (addH && cx < add_cols) {
                    uint32_t uh = *(const uint32_t*)((const char*)addH + ((size_t)r * ld_add + cx) * 2);
                    uint32_t ul = *(const uint32_t*)((const char*)addL + ((size_t)r * ld_add + cx) * 2);
                    v0 += bflo(uh) + bflo(ul);
                    v1 += bfhi(uh) + bfhi(ul);
                }
                if (do_relu) { v0 = fmaxf(v0, 0.0f); v1 = fmaxf(v1, 0.0f); }
                if (outF && cx < ncolF)
                    *(float2*)(outF + (size_t)r * ldF + cx) = make_float2(v0, v1);
                if (PH) {
                    uint32_t ph, pl;
                    pack2(v0, v1, ph, pl);
                    *(uint32_t*)((char*)PH + ((size_t)r * ldP + cx) * 2) = ph;
                    *(uint32_t*)((char*)PL + ((size_t)r * ldP + cx) * 2) = pl;
                }
            }
        }
}

// ---------------- launch ----------------------------------------------------
extern "C" void kernel_launch(void* const* d_in, const int* in_sizes, int n_in,
                              void* d_out, int out_size)
{
    const float* x      = (const float*)d_in[0];
    ConvPtrs cw;
    for (int i = 0; i < 8; i++) cw.w[i] = (const float*)d_in[1 + i];
    const float* conv_b = (const float*)d_in[9];
    const float* W      = (const float*)d_in[10];
    const float* lora_A = (const float*)d_in[11];
    const float* lora_B = (const float*)d_in[12];
    const float* ip_w   = (const float*)d_in[13];
    const float* ip_b   = (const float*)d_in[14];
    const float* out_w  = (const float*)d_in[15];
    const float* out_b  = (const float*)d_in[16];
    float* out = (float*)d_out;

    __nv_bfloat16 *featH, *featL, *ipwH, *ipwL, *WH, *WL, *owH, *owL;
    __nv_bfloat16 *P0H, *P0L, *P1H, *P1L, *OPH, *OPL, *laH, *laL, *lbtH, *lbtL;
    float* part;
    cudaGetSymbolAddress((void**)&featH, g_featH);
    cudaGetSymbolAddress((void**)&featL, g_featL);
    cudaGetSymbolAddress((void**)&ipwH,  g_ipwH);
    cudaGetSymbolAddress((void**)&ipwL,  g_ipwL);
    cudaGetSymbolAddress((void**)&WH,    g_WH);
    cudaGetSymbolAddress((void**)&WL,    g_WL);
    cudaGetSymbolAddress((void**)&owH,   g_owH);
    cudaGetSymbolAddress((void**)&owL,   g_owL);
    cudaGetSymbolAddress((void**)&P0H,   g_P0H);
    cudaGetSymbolAddress((void**)&P0L,   g_P0L);
    cudaGetSymbolAddress((void**)&P1H,   g_P1H);
    cudaGetSymbolAddress((void**)&P1L,   g_P1L);
    cudaGetSymbolAddress((void**)&OPH,   g_OPH);
    cudaGetSymbolAddress((void**)&OPL,   g_OPL);
    cudaGetSymbolAddress((void**)&laH,   g_laH);
    cudaGetSymbolAddress((void**)&laL,   g_laL);
    cudaGetSymbolAddress((void**)&lbtH,  g_lbtH);
    cudaGetSymbolAddress((void**)&lbtL,  g_lbtL);
    cudaGetSymbolAddress((void**)&part,  g_part);

    const int SMEM = 3 * 4 * 128 * 32 * 2;   // 3 stages x 32KB = 98304
    cudaFuncSetAttribute(mma_gemm<3, 32, false, false>, cudaFuncAttributeMaxDynamicSharedMemorySize, SMEM);
    cudaFuncSetAttribute(mma_gemm<3, 32, false, true>,  cudaFuncAttributeMaxDynamicSharedMemorySize, SMEM);
    cudaFuncSetAttribute(mma_gemm<3, 32, true, false>,  cudaFuncAttributeMaxDynamicSharedMemorySize, SMEM);

    // ---- capture-fork side streams: created ONCE on first call (before the
    // harness's pre-capture memory baseline). Reused across calls so nothing
    // is allocated during capture; teardown checkpoint stays at delta 0.
    static cudaStream_t s1 = nullptr, s2 = nullptr;
    static cudaEvent_t eF1 = nullptr, eF2 = nullptr, eJ1 = nullptr, eJ2 = nullptr;
    if (s1 == nullptr) {
        cudaStreamCreateWithFlags(&s1, cudaStreamNonBlocking);
        cudaStreamCreateWithFlags(&s2, cudaStreamNonBlocking);
        cudaEventCreateWithFlags(&eF1, cudaEventDisableTiming);
        cudaEventCreateWithFlags(&eF2, cudaEventDisableTiming);
        cudaEventCreateWithFlags(&eJ1, cudaEventDisableTiming);
        cudaEventCreateWithFlags(&eJ2, cudaEventDisableTiming);
    }

    // fork
    cudaEventRecord(eF1, 0);
    cudaEventRecord(eF2, 0);
    cudaStreamWaitEvent(s1, eF1, 0);
    cudaStreamWaitEvent(s2, eF2, 0);

    // ---- stream0: fused(conv + ip_w pack) -> t0 -> epi0 ----
    fused_prep<<<BATCH + (KPAD / 64) * (SEN / 64), 256>>>(
        x, cw, conv_b, featH, featL, ip_w, ipwH, ipwL);
    mma_gemm<3, 32, false, false><<<dim3(SEN / 128, 8, 4), 256, SMEM>>>(
        featH, featL, KPAD, ipwH, ipwL, KPAD, 832,
        nullptr, nullptr, nullptr, 0, 0, 0,
        part, 1024, 1024, nullptr, nullptr, 0, nullptr, BATCH * 1024);
    epi_reduce<<<2048, 256>>>(part, 4, 512, ip_b, nullptr, nullptr, 0, 1,
                              nullptr, 0, 1024, P0H, P0L, TOT);

    // ---- s1: lora packs + W_eff^T ----
    split_copy<<<(TOT * 64 / 8 + 255) / 256, 256, 0, s1>>>(lora_A, laH, laL, TOT * 64 / 8);
    pack_wT<<<dim3(1, TOT / 64), 256, 0, s1>>>(lora_B, TOT, TOT, 64, 64, lbtH, lbtL);
    mma_gemm<3, 32, true, false><<<dim3(32, 32), 256, SMEM, s1>>>(
        lbtH, lbtL, 64, laH, laL, 64, 64,
        nullptr, nullptr, nullptr, 0, 0, 0,
        nullptr, 0, 0, WH, WL, TOT, W, 0);

    // ---- s2: out_w pack ----
    pack_wT<<<dim3(1024 / 64, NOUT_PAD / 64), 256, 0, s2>>>(out_w, NOUT, NOUT, 1024, 1024, owH, owL);

    // join
    cudaEventRecord(eJ1, s1);
    cudaEventRecord(eJ2, s2);
    cudaStreamWaitEvent(0, eJ1, 0);
    cudaStreamWaitEvent(0, eJ2, 0);

    // ---- t1 (K = 1024) ----
    mma_gemm<3, 32, false, true><<<dim3(8, TOT / 128), 256, SMEM>>>(
        P0H, P0L, TOT, WH, WL, TOT, 1024,
        nullptr, P0H, P0L, 1024, TOT, 1,
        nullptr, 0, 0, P1H, P1L, TOT, nullptr, 0);
    // ---- t2 ----
    mma_gemm<3, 32, false, true><<<dim3(8, TOT / 128), 256, SMEM>>>(
        P1H, P1L, TOT, WH, WL, TOT, TOT,
        nullptr, P1H, P1L, TOT, TOT, 1,
        nullptr, 0, 0, P0H, P0L, TOT, nullptr, 0);
    // ---- t3 ----
    mma_gemm<3, 32, false, true><<<dim3(8, TOT / 128), 256, SMEM>>>(
        P0H, P0L, TOT, WH, WL, TOT, TOT,
        nullptr, P0H, P0L, TOT, TOT, 1,
        nullptr, 0, 0, P1H, P1L, TOT, nullptr, 0);

    // ---- t4 split-K=4 -> partials ----
    mma_gemm<3, 32, false, false><<<dim3(8, 8, 4), 256, SMEM>>>(
        P1H, P1L, TOT, WH + (size_t)3072 * TOT, WL + (size_t)3072 * TOT, TOT, 1024,
        nullptr, nullptr, nullptr, 0, 0, 0,
        part, 1024, 1024, nullptr, nullptr, 0, nullptr, BATCH * 1024);
    epi_reduce<<<2048, 256>>>(part, 4, 512, nullptr, P1H + 3072, P1L + 3072, TOT, 1,
                              nullptr, 0, 1024, OPH, OPL, 1024);

    // ---- out GEMM split-K=2 -> partials -> reduce+bias ----
    mma_gemm<3, 32, false, false><<<dim3(NOUT_PAD / 128, 8, 2), 256, SMEM>>>(
        OPH, OPL, 1024, owH, owL, 1024, 512,
        nullptr, nullptr, nullptr, 0, 0, 0,
        part, 2048, 2048, nullptr, nullptr, 0, nullptr, BATCH * 2048);
    epi_reduce<<<4096, 256>>>(part, 2, 1024, out_b, nullptr, nullptr, 0, 0,
                              out, NOUT, NOUT, nullptr, nullptr, 0);
}

// round 15
// speedup vs baseline: 1.0271x; 1.0271x over previous
#include <cuda_runtime.h>
#include <cuda_bf16.h>
#include <cstdint>

#define BATCH    1024
#define TOT      4096
#define SEN      1024
#define CNNOUT   3264
#define KPAD     3328
#define NOUT     1968
#define NOUT_PAD 2048

// ---------------- scratch device globals (no allocations) -------------------
__device__ __align__(256) __nv_bfloat16 g_featH[(size_t)BATCH * KPAD];
__device__ __align__(256) __nv_bfloat16 g_featL[(size_t)BATCH * KPAD];
__device__ __align__(256) __nv_bfloat16 g_ipwH [(size_t)SEN * KPAD];
__device__ __align__(256) __nv_bfloat16 g_ipwL [(size_t)SEN * KPAD];
__device__ __align__(256) __nv_bfloat16 g_WH   [(size_t)TOT * TOT];
__device__ __align__(256) __nv_bfloat16 g_WL   [(size_t)TOT * TOT];
__device__ __align__(256) __nv_bfloat16 g_owH  [(size_t)NOUT_PAD * 1024];
__device__ __align__(256) __nv_bfloat16 g_owL  [(size_t)NOUT_PAD * 1024];
__device__ __align__(256) __nv_bfloat16 g_P0H  [(size_t)BATCH * TOT];
__device__ __align__(256) __nv_bfloat16 g_P0L  [(size_t)BATCH * TOT];
__device__ __align__(256) __nv_bfloat16 g_P1H  [(size_t)BATCH * TOT];
__device__ __align__(256) __nv_bfloat16 g_P1L  [(size_t)BATCH * TOT];
__device__ __align__(256) __nv_bfloat16 g_OPH  [(size_t)BATCH * 1024];
__device__ __align__(256) __nv_bfloat16 g_OPL  [(size_t)BATCH * 1024];
__device__ __align__(256) __nv_bfloat16 g_laH [(size_t)TOT * 64];
__device__ __align__(256) __nv_bfloat16 g_laL [(size_t)TOT * 64];
__device__ __align__(256) __nv_bfloat16 g_lbtH[(size_t)TOT * 64];
__device__ __align__(256) __nv_bfloat16 g_lbtL[(size_t)TOT * 64];
__device__ __align__(256) float g_part[(size_t)4 * BATCH * 1024];   // split-K partials (16MB)

// ---------------- helpers ----------------------------------------------------
__device__ __forceinline__ uint32_t smem_u32(const void* p) {
    uint32_t a;
    asm("{ .reg .u64 t; cvta.to.shared.u64 t, %1; cvt.u32.u64 %0, t; }" : "=r"(a) : "l"(p));
    return a;
}
__device__ __forceinline__ void cpa(uint32_t dst, const void* src) {
    asm volatile("cp.async.cg.shared.global [%0], [%1], 16;" :: "r"(dst), "l"(src));
}
#define CP_COMMIT() asm volatile("cp.async.commit_group;")
#define CP_WAIT0()  asm volatile("cp.async.wait_group 0;")
#define CP_WAIT1()  asm volatile("cp.async.wait_group 1;")

__device__ __forceinline__ void ldsm4(uint32_t* r, uint32_t addr) {
    asm volatile("ldmatrix.sync.aligned.m8n8.x4.shared.b16 {%0,%1,%2,%3}, [%4];"
                 : "=r"(r[0]), "=r"(r[1]), "=r"(r[2]), "=r"(r[3]) : "r"(addr));
}
__device__ __forceinline__ void mma16816(float* c, const uint32_t* a, const uint32_t* b) {
    asm volatile("mma.sync.aligned.m16n8k16.row.col.f32.bf16.bf16.f32 "
                 "{%0,%1,%2,%3}, {%4,%5,%6,%7}, {%8,%9}, {%0,%1,%2,%3};"
                 : "+f"(c[0]), "+f"(c[1]), "+f"(c[2]), "+f"(c[3])
                 : "r"(a[0]), "r"(a[1]), "r"(a[2]), "r"(a[3]), "r"(b[0]), "r"(b[1]));
}

__device__ __forceinline__ void split8(const float* v, uint4& uh, uint4& ul) {
    uint32_t h[4], l[4];
#pragma unroll
    for (int q = 0; q < 4; q++) {
        __nv_bfloat16 b0 = __float2bfloat16(v[2 * q]);
        __nv_bfloat16 b1 = __float2bfloat16(v[2 * q + 1]);
        float r0 = v[2 * q]     - __bfloat162float(b0);
        float r1 = v[2 * q + 1] - __bfloat162float(b1);
        __nv_bfloat16 c0 = __float2bfloat16(r0);
        __nv_bfloat16 c1 = __float2bfloat16(r1);
        h[q] = (uint32_t)__bfloat16_as_ushort(b0) | ((uint32_t)__bfloat16_as_ushort(b1) << 16);
        l[q] = (uint32_t)__bfloat16_as_ushort(c0) | ((uint32_t)__bfloat16_as_ushort(c1) << 16);
    }
    uh = make_uint4(h[0], h[1], h[2], h[3]);
    ul = make_uint4(l[0], l[1], l[2], l[3]);
}
__device__ __forceinline__ void pack2(float v0, float v1, uint32_t& ph, uint32_t& pl) {
    __nv_bfloat16 h0 = __float2bfloat16(v0);
    __nv_bfloat16 h1 = __float2bfloat16(v1);
    __nv_bfloat16 q0 = __float2bfloat16(v0 - __bfloat162float(h0));
    __nv_bfloat16 q1 = __float2bfloat16(v1 - __bfloat162float(h1));
    ph = (uint32_t)__bfloat16_as_ushort(h0) | ((uint32_t)__bfloat16_as_ushort(h1) << 16);
    pl = (uint32_t)__bfloat16_as_ushort(q0) | ((uint32_t)__bfloat16_as_ushort(q1) << 16);
}
__device__ __forceinline__ float bflo(uint32_t u) {
    return __bfloat162float(__ushort_as_bfloat16((unsigned short)(u & 0xFFFF)));
}
__device__ __forceinline__ float bfhi(uint32_t u) {
    return __bfloat162float(__ushort_as_bfloat16((unsigned short)(u >> 16)));
}

struct ConvPtrs { const float* w[8]; };

// ---------------- fused: conv feature extraction + ip_w pack ----------------
__global__ __launch_bounds__(256) void fused_prep(
    const float* __restrict__ x, ConvPtrs cw, const float* __restrict__ conv_b,
    __nv_bfloat16* __restrict__ fH, __nv_bfloat16* __restrict__ fL,
    const float* __restrict__ ipw,
    __nv_bfloat16* __restrict__ iH, __nv_bfloat16* __restrict__ iL)
{
    __shared__ float sm[64 * 65];
    const int tid = threadIdx.x;
    const int bid = blockIdx.x;

    if (bid < BATCH) {
        float* xs = sm;
        const float* xb = x + bid * 512;
        for (int i = tid; i < 512; i += 256) xs[i] = xb[i];
        __syncthreads();

        const int offs[9] = {0, 1024, 1808, 2384, 2784, 3040, 3184, 3248, 3264};
        for (int o = tid; o < KPAD; o += 256) {
            if (o >= CNNOUT) {
                fH[(size_t)bid * KPAD + o] = __ushort_as_bfloat16(0);
                fL[(size_t)bid * KPAD + o] = __ushort_as_bfloat16(0);
                continue;
            }
            int k = 1;
            while (o >= offs[k]) k++;
            int local = o - offs[k - 1];
            int H = 9 - k;
            int f = local / (H * H);
            int rem = local - f * H * H;
            int i0 = rem / H;
            int j0 = rem - i0 * H;

            const float* w = cw.w[k - 1] + f * 8 * k * k;
            float acc = conv_b[(k - 1) * 16 + f];
            for (int c = 0; c < 8; c++) {
                const float* wc = w + c * k * k;
                for (int p = 0; p < k; p++)
                    for (int q = 0; q < k; q++)
                        acc += xs[((i0 + p) * 8 + (j0 + q)) * 8 + c] * wc[p * k + q];
            }
            float e = fmaxf(acc, 0.0f);
            __nv_bfloat16 bh = __float2bfloat16(e);
            __nv_bfloat16 bl = __float2bfloat16(e - __bfloat162float(bh));
            fH[(size_t)bid * KPAD + o] = bh;
            fL[(size_t)bid * KPAD + o] = bl;
        }
    } else {
        const int pb = bid - BATCH;
        const int k0 = (pb % (KPAD / 64)) * 64;
        const int n0 = (pb / (KPAD / 64)) * 64;

        for (int i = tid; i < 4096; i += 256) {
            int k = i >> 6, n = i & 63;
            int gn = n0 + n, gk = k0 + k;
            sm[k * 65 + n] = (gn < SEN && gk < CNNOUT) ? ipw[(size_t)gk * SEN + gn] : 0.0f;
        }
        __syncthreads();

        for (int it = tid; it < 512; it += 256) {
            int n = it & 63, kg = it >> 6;
            float v[8];
#pragma unroll
            for (int j = 0; j < 8; j++) v[j] = sm[(kg * 8 + j) * 65 + n];
            uint4 uh, ul;
            split8(v, uh, ul);
            size_t o = (size_t)(n0 + n) * KPAD + k0 + kg * 8;
            *(uint4*)((char*)iH + o * 2) = uh;
            *(uint4*)((char*)iL + o * 2) = ul;
        }
    }
}

// ---------------- pack [K,N] fp32 weight transposed -> [N,K] hi/lo bf16 -----
__global__ __launch_bounds__(256) void pack_wT(const float* __restrict__ w,
                                               int ldw, int ntrue, int ktrue, int ldk,
                                               __nv_bfloat16* __restrict__ H,
                                               __nv_bfloat16* __restrict__ L)
{
    __shared__ float sm[64 * 65];
    const int k0 = blockIdx.x * 64, n0 = blockIdx.y * 64;
    const int tid = threadIdx.x;

    for (int i = tid; i < 4096; i += 256) {
        int k = i >> 6, n = i & 63;
        int gn = n0 + n, gk = k0 + k;
        sm[k * 65 + n] = (gn < ntrue && gk < ktrue) ? w[(size_t)gk * ldw + gn] : 0.0f;
    }
    __syncthreads();

    for (int it = tid; it < 512; it += 256) {
        int n = it & 63, kg = it >> 6;
        float v[8];
#pragma unroll
        for (int j = 0; j < 8; j++) v[j] = sm[(kg * 8 + j) * 65 + n];
        uint4 uh, ul;
        split8(v, uh, ul);
        size_t o = (size_t)(n0 + n) * ldk + k0 + kg * 8;
        *(uint4*)((char*)H + o * 2) = uh;
        *(uint4*)((char*)L + o * 2) = ul;
    }
}

// ---------------- straight split-copy fp32 -> hi/lo bf16 --------------------
__global__ void split_copy(const float* __restrict__ in,
                           __nv_bfloat16* __restrict__ H,
                           __nv_bfloat16* __restrict__ L, int n8)
{
    int i = blockIdx.x * blockDim.x + threadIdx.x;
    if (i >= n8) return;
    float v[8];
    *(float4*)(v)     = *(const float4*)(in + (size_t)i * 8);
    *(float4*)(v + 4) = *(const float4*)(in + (size_t)i * 8 + 4);
    uint4 uh, ul;
    split8(v, uh, ul);
    *(uint4*)((char*)H + (size_t)i * 16) = uh;
    *(uint4*)((char*)L + (size_t)i * 16) = ul;
}

// ---------------- generic split-K reduce epilogue ---------------------------
__global__ __launch_bounds__(256) void epi_reduce(
    const float* __restrict__ part, int nz, int partW2,
    const float* __restrict__ bias,
    int do_relu,
    float* __restrict__ fOut, int ldO, int ncolO,
    __nv_bfloat16* __restrict__ PH, __nv_bfloat16* __restrict__ PL, int ldP)
{
    const int i = blockIdx.x * blockDim.x + threadIdx.x;
    const int r = i / partW2;
    const int c2 = (i - r * partW2) * 2;
    const int partW = partW2 * 2;
    if (r >= BATCH) return;
    float v0 = 0.0f, v1 = 0.0f;
    for (int z = 0; z < nz; z++) {
        float2 p = *(const float2*)(part + (size_t)z * BATCH * partW + (size_t)r * partW + c2);
        v0 += p.x; v1 += p.y;
    }
    if (bias && c2 + 1 < ncolO) {
        float2 b = *(const float2*)(bias + c2);
        v0 += b.x; v1 += b.y;
    }
    if (do_relu) { v0 = fmaxf(v0, 0.0f); v1 = fmaxf(v1, 0.0f); }
    if (fOut && c2 + 1 < ncolO)
        *(float2*)(fOut + (size_t)r * ldO + c2) = make_float2(v0, v1);
    if (PH) {
        uint32_t ph, pl;
        pack2(v0, v1, ph, pl);
        *(uint32_t*)((char*)PH + ((size_t)r * ldP + c2) * 2) = ph;
        *(uint32_t*)((char*)PL + ((size_t)r * ldP + c2) * 2) = pl;
    }
}

// ---------------- mma.sync bf16-split GEMM ----------------------------------
// 256 threads, 2 CTAs/SM (launch_bounds cap 128 regs). Tile 128x128,
// warp tile 64x32 (2Mx4N warps). KCH=32 chunks, 3 stages x 32KB = 96KB smem.
// ONE barrier per chunk; both kk-slices' B fragments prefetched after the
// barrier, next-chunk cp.async issued between slice0 and slice1 MMAs.
// Residual connection is FOLDED INTO the weight (W' = W_eff + I), so no
// addend path exists. 3-term bf16 split (drop lo*lo). z = split-K slice.
// MSWAP: blockIdx.x = m-tile, blockIdx.y = n-tile. WEFF: lora+mask+I epilogue.
template<int STAGES, int KCH, bool WEFF, bool MSWAP>
__global__ __launch_bounds__(256, 2)
void mma_gemm(const __nv_bfloat16* __restrict__ AH, const __nv_bfloat16* __restrict__ AL, int lda,
              const __nv_bfloat16* __restrict__ BH, const __nv_bfloat16* __restrict__ BL, int ldb,
              int K,
              const float* __restrict__ bias, int do_relu,
              float* __restrict__ outF, int ldF, int ncolF,
              __nv_bfloat16* __restrict__ PH, __nv_bfloat16* __restrict__ PL, int ldP,
              const float* __restrict__ Wsrc, int partStride)
{
    static_assert(KCH == 32, "chunk layout assumes KCH==32 (2 kk-slices)");
    constexpr int GPC   = KCH / 8;                 // 16B granules per row
    constexpr int AHALF = 128 * KCH * 2;
    constexpr int STG   = 4 * AHALF;
    extern __shared__ __align__(128) char smc[];

    const int tid = threadIdx.x, l = tid & 31, wid = tid >> 5;
    const int nblk = MSWAP ? blockIdx.y : blockIdx.x;
    const int mblk = MSWAP ? blockIdx.x : blockIdx.y;
    const int zo = blockIdx.z;
    const int KB = K / KCH;
    const uint32_t smb = smem_u32(smc);
    const int mrow0 = mblk * 128;
    const int nrow0 = nblk * 128;

    AH += (size_t)zo * K; AL += (size_t)zo * K;
    BH += (size_t)zo * K; BL += (size_t)zo * K;
    if (outF) outF += (size_t)zo * partStride;

    auto swof = [](int r, uint32_t g) -> uint32_t {
        return (uint32_t)r * 64 + ((g ^ (uint32_t)((r >> 1) & 3)) << 4);
    };

    auto load_chunk = [&](int s, int c) {
        const int kof = c * KCH;
        const uint32_t sb = smb + (uint32_t)s * STG;
#pragma unroll
        for (int it = 0; it < (4 * 128 * GPC) / 256; it++) {
            int idx = tid + it * 256;
            int mat = idx / (128 * GPC);               // 0=AH 1=AL 2=BH 3=BL
            int j = idx - mat * (128 * GPC);
            int r = j / GPC, g = j - r * GPC;
            const __nv_bfloat16* src =
                (mat == 0 ? AH : mat == 1 ? AL : mat == 2 ? BH : BL);
            const int row0 = (mat < 2) ? mrow0 : nrow0;
            const int ld   = (mat < 2) ? lda : ldb;
            cpa(sb + (uint32_t)mat * AHALF + swof(r, (uint32_t)g),
                src + (size_t)(row0 + r) * ld + kof + g * 8);
        }
    };

    const int mw = wid & 1, nw = wid >> 1;
    const int mbase = mw * 64, nbase = nw * 32;
    const int rA0 = mbase + (l & 7) + ((l >> 3) & 1) * 8;
    const int rB0 = nbase + (l & 7) + ((l >> 3) & 1) * 8;
    const int gsel = l >> 4;

    float acc[4][4][4];
#pragma unroll
    for (int a = 0; a < 4; a++)
#pragma unroll
        for (int b = 0; b < 4; b++)
#pragma unroll
            for (int c = 0; c < 4; c++) acc[a][b][c] = 0.0f;

    auto prefetch_B = [&](uint32_t base, int kk, uint32_t bh[4][2], uint32_t bl[4][2]) {
        const uint32_t g = 2 * kk + gsel;
#pragma unroll
        for (int p = 0; p < 2; p++) {
            uint32_t t0[4], t1[4];
            uint32_t addr = base + 2 * AHALF + swof(rB0 + p * 16, g);
            ldsm4(t0, addr);
            ldsm4(t1, addr + AHALF);
            bh[2 * p][0] = t0[0]; bh[2 * p][1] = t0[2];
            bh[2 * p + 1][0] = t0[1]; bh[2 * p + 1][1] = t0[3];
            bl[2 * p][0] = t1[0]; bl[2 * p][1] = t1[2];
            bl[2 * p + 1][0] = t1[1]; bl[2 * p + 1][1] = t1[3];
        }
    };

    auto mma_slice = [&](uint32_t base, int kk, uint32_t bh[4][2], uint32_t bl[4][2]) {
        const uint32_t g = 2 * kk + gsel;
#pragma unroll
        for (int mt = 0; mt < 4; mt++) {
            uint32_t ah[4], al_[4];
            uint32_t addr = base + swof(rA0 + mt * 16, g);
            ldsm4(ah, addr);
            ldsm4(al_, addr + AHALF);
#pragma unroll
            for (int nt = 0; nt < 4; nt++) mma16816(acc[mt][nt], ah, bh[nt]);
#pragma unroll
            for (int nt = 0; nt < 4; nt++) mma16816(acc[mt][nt], ah, bl[nt]);
#pragma unroll
            for (int nt = 0; nt < 4; nt++) mma16816(acc[mt][nt], al_, bh[nt]);
        }
    };

    // pipeline: prologue commits exactly STAGES-1 groups (empty groups are
    // in-order fences; required when KB < STAGES-1). One barrier per chunk.
#pragma unroll
    for (int s = 0; s < STAGES - 1; s++) {
        if (s < KB) load_chunk(s, s);
        CP_COMMIT();
    }
    for (int c = 0; c < KB; c++) {
        const int s = c % STAGES;
        if (STAGES == 3) { CP_WAIT1(); } else { CP_WAIT0(); }
        __syncthreads();
        const uint32_t base = smb + (uint32_t)s * STG;

        uint32_t b0h[4][2], b0l[4][2], b1h[4][2], b1l[4][2];
        prefetch_B(base, 0, b0h, b0l);
        prefetch_B(base, 1, b1h, b1l);
        mma_slice(base, 0, b0h, b0l);
        if (c + STAGES - 1 < KB) load_chunk((c + STAGES - 1) % STAGES, c + STAGES - 1);
        CP_COMMIT();
        mma_slice(base, 1, b1h, b1l);
    }

    const int rr = l >> 2, cc = (l & 3) * 2;

    if (WEFF) {
        // acc = lora product. W' = mask(W)*(W + 2*lora) + I  (residual folded)
        __syncthreads();
        float* Wt = (float*)smc;   // [n_local][kk_local], stride 129
        for (int i = tid; i < 128 * 128; i += 256) {
            int kk = i >> 7, n = i & 127;
            Wt[n * 129 + kk] = Wsrc[(size_t)(nrow0 + kk) * TOT + mrow0 + n];
        }
        __syncthreads();
#pragma unroll
        for (int mt = 0; mt < 4; mt++)
#pragma unroll
            for (int h = 0; h < 2; h++) {
                const int rl = mbase + mt * 16 + rr + h * 8;
                const int rg = mrow0 + rl;           // dest index
                const size_t r = (size_t)rg;
#pragma unroll
                for (int nt = 0; nt < 4; nt++) {
                    const int cl = nbase + nt * 8 + cc;
                    const int cx = nrow0 + cl;       // src index
                    float w0 = Wt[rl * 129 + cl];
                    float w1 = Wt[rl * 129 + cl + 1];
                    float v0 = (w0 == 0.0f) ? 0.0f : (w0 + 2.0f * acc[mt][nt][h * 2 + 0]);
                    float v1 = (w1 == 0.0f) ? 0.0f : (w1 + 2.0f * acc[mt][nt][h * 2 + 1]);
                    if (rg == cx)     v0 += 1.0f;
                    if (rg == cx + 1) v1 += 1.0f;
                    uint32_t ph, pl;
                    pack2(v0, v1, ph, pl);
                    *(uint32_t*)((char*)PH + (r * ldP + cx) * 2) = ph;
                    *(uint32_t*)((char*)PL + (r * ldP + cx) * 2) = pl;
                }
            }
        return;
    }

    const int growb = mrow0 + mbase;
    const int gcolb = nrow0 + nbase;
#pragma unroll
    for (int mt = 0; mt < 4; mt++)
#pragma unroll
        for (int h = 0; h < 2; h++) {
            const int r = growb + mt * 16 + rr + h * 8;
#pragma unroll
            for (int nt = 0; nt < 4; nt++) {
                const int cx = gcolb + nt * 8 + cc;
                float v0 = acc[mt][nt][h * 2 + 0];
                float v1 = acc[mt][nt][h * 2 + 1];
                if (bias && cx < ncolF) {
                    float2 bv = *(const float2*)(bias + cx);
                    v0 += bv.x; v1 += bv.y;
                }
                if (do_relu) { v0 = fmaxf(v0, 0.0f); v1 = fmaxf(v1, 0.0f); }
                if (outF && cx < ncolF)
                    *(float2*)(outF + (size_t)r * ldF + cx) = make_float2(v0, v1);
                if (PH) {
                    uint32_t ph, pl;
                    pack2(v0, v1, ph, pl);
                    *(uint32_t*)((char*)PH + ((size_t)r * ldP + cx) * 2) = ph;
                    *(uint32_t*)((char*)PL + ((size_t)r * ldP + cx) * 2) = pl;
                }
            }
        }
}

// ---------------- launch ----------------------------------------------------
extern "C" void kernel_launch(void* const* d_in, const int* in_sizes, int n_in,
                              void* d_out, int out_size)
{
    const float* x      = (const float*)d_in[0];
    ConvPtrs cw;
    for (int i = 0; i < 8; i++) cw.w[i] = (const float*)d_in[1 + i];
    const float* conv_b = (const float*)d_in[9];
    const float* W      = (const float*)d_in[10];
    const float* lora_A = (const float*)d_in[11];
    const float* lora_B = (const float*)d_in[12];
    const float* ip_w   = (const float*)d_in[13];
    const float* ip_b   = (const float*)d_in[14];
    const float* out_w  = (const float*)d_in[15];
    const float* out_b  = (const float*)d_in[16];
    float* out = (float*)d_out;

    __nv_bfloat16 *featH, *featL, *ipwH, *ipwL, *WH, *WL, *owH, *owL;
    __nv_bfloat16 *P0H, *P0L, *P1H, *P1L, *OPH, *OPL, *laH, *laL, *lbtH, *lbtL;
    float* part;
    cudaGetSymbolAddress((void**)&featH, g_featH);
    cudaGetSymbolAddress((void**)&featL, g_featL);
    cudaGetSymbolAddress((void**)&ipwH,  g_ipwH);
    cudaGetSymbolAddress((void**)&ipwL,  g_ipwL);
    cudaGetSymbolAddress((void**)&WH,    g_WH);
    cudaGetSymbolAddress((void**)&WL,    g_WL);
    cudaGetSymbolAddress((void**)&owH,   g_owH);
    cudaGetSymbolAddress((void**)&owL,   g_owL);
    cudaGetSymbolAddress((void**)&P0H,   g_P0H);
    cudaGetSymbolAddress((void**)&P0L,   g_P0L);
    cudaGetSymbolAddress((void**)&P1H,   g_P1H);
    cudaGetSymbolAddress((void**)&P1L,   g_P1L);
    cudaGetSymbolAddress((void**)&OPH,   g_OPH);
    cudaGetSymbolAddress((void**)&OPL,   g_OPL);
    cudaGetSymbolAddress((void**)&laH,   g_laH);
    cudaGetSymbolAddress((void**)&laL,   g_laL);
    cudaGetSymbolAddress((void**)&lbtH,  g_lbtH);
    cudaGetSymbolAddress((void**)&lbtL,  g_lbtL);
    cudaGetSymbolAddress((void**)&part,  g_part);

    const int SMEM = 3 * 4 * 128 * 32 * 2;   // 3 stages x 32KB = 98304
    cudaFuncSetAttribute(mma_gemm<3, 32, false, false>, cudaFuncAttributeMaxDynamicSharedMemorySize, SMEM);
    cudaFuncSetAttribute(mma_gemm<3, 32, false, true>,  cudaFuncAttributeMaxDynamicSharedMemorySize, SMEM);
    cudaFuncSetAttribute(mma_gemm<3, 32, true, false>,  cudaFuncAttributeMaxDynamicSharedMemorySize, SMEM);

    // ---- capture-fork side streams: created ONCE on first call (before the
    // harness's pre-capture memory baseline). Reused across calls so nothing
    // is allocated during capture; teardown checkpoint stays at delta 0.
    static cudaStream_t s1 = nullptr, s2 = nullptr;
    static cudaEvent_t eF1 = nullptr, eF2 = nullptr, eJ1 = nullptr, eJ2 = nullptr;
    if (s1 == nullptr) {
        cudaStreamCreateWithFlags(&s1, cudaStreamNonBlocking);
        cudaStreamCreateWithFlags(&s2, cudaStreamNonBlocking);
        cudaEventCreateWithFlags(&eF1, cudaEventDisableTiming);
        cudaEventCreateWithFlags(&eF2, cudaEventDisableTiming);
        cudaEventCreateWithFlags(&eJ1, cudaEventDisableTiming);
        cudaEventCreateWithFlags(&eJ2, cudaEventDisableTiming);
    }

    // fork
    cudaEventRecord(eF1, 0);
    cudaEventRecord(eF2, 0);
    cudaStreamWaitEvent(s1, eF1, 0);
    cudaStreamWaitEvent(s2, eF2, 0);

    // ---- stream0: fused(conv + ip_w pack) -> t0 -> epi0 ----
    fused_prep<<<BATCH + (KPAD / 64) * (SEN / 64), 256>>>(
        x, cw, conv_b, featH, featL, ip_w, ipwH, ipwL);
    mma_gemm<3, 32, false, false><<<dim3(SEN / 128, 8, 4), 256, SMEM>>>(
        featH, featL, KPAD, ipwH, ipwL, KPAD, 832,
        nullptr, 0, part, 1024, 1024, nullptr, nullptr, 0, nullptr, BATCH * 1024);
    epi_reduce<<<2048, 256>>>(part, 4, 512, ip_b, 1,
                              nullptr, 0, 1024, P0H, P0L, TOT);

    // ---- s1: lora packs + W' = W_eff + I ----
    split_copy<<<(TOT * 64 / 8 + 255) / 256, 256, 0, s1>>>(lora_A, laH, laL, TOT * 64 / 8);
    pack_wT<<<dim3(1, TOT / 64), 256, 0, s1>>>(lora_B, TOT, TOT, 64, 64, lbtH, lbtL);
    mma_gemm<3, 32, true, false><<<dim3(32, 32), 256, SMEM, s1>>>(
        lbtH, lbtL, 64, laH, laL, 64, 64,
        nullptr, 0, nullptr, 0, 0, WH, WL, TOT, W, 0);

    // ---- s2: out_w pack ----
    pack_wT<<<dim3(1024 / 64, NOUT_PAD / 64), 256, 0, s2>>>(out_w, NOUT, NOUT, 1024, 1024, owH, owL);

    // join
    cudaEventRecord(eJ1, s1);
    cudaEventRecord(eJ2, s2);
    cudaStreamWaitEvent(0, eJ1, 0);
    cudaStreamWaitEvent(0, eJ2, 0);

    // ---- t1: state1 = relu(state0 @ W')   (K = 1024) ----
    mma_gemm<3, 32, false, true><<<dim3(8, TOT / 128), 256, SMEM>>>(
        P0H, P0L, TOT, WH, WL, TOT, 1024,
        nullptr, 1, nullptr, 0, 0, P1H, P1L, TOT, nullptr, 0);
    // ---- t2 ----
    mma_gemm<3, 32, false, true><<<dim3(8, TOT / 128), 256, SMEM>>>(
        P1H, P1L, TOT, WH, WL, TOT, TOT,
        nullptr, 1, nullptr, 0, 0, P0H, P0L, TOT, nullptr, 0);
    // ---- t3 ----
    mma_gemm<3, 32, false, true><<<dim3(8, TOT / 128), 256, SMEM>>>(
        P0H, P0L, TOT, WH, WL, TOT, TOT,
        nullptr, 1, nullptr, 0, 0, P1H, P1L, TOT, nullptr, 0);

    // ---- t4: O = relu(state3 @ W'[:, 3072:])  split-K=4 -> partials ----
    mma_gemm<3, 32, false, false><<<dim3(8, 8, 4), 256, SMEM>>>(
        P1H, P1L, TOT, WH + (size_t)3072 * TOT, WL + (size_t)3072 * TOT, TOT, 1024,
        nullptr, 0, part, 1024, 1024, nullptr, nullptr, 0, nullptr, BATCH * 1024);
    epi_reduce<<<2048, 256>>>(part, 4, 512, nullptr, 1,
                              nullptr, 0, 1024, OPH, OPL, 1024);

    // ---- out GEMM split-K=2 -> partials -> reduce+bias ----
    mma_gemm<3, 32, false, false><<<dim3(NOUT_PAD / 128, 8, 2), 256, SMEM>>>(
        OPH, OPL, 1024, owH, owL, 1024, 512,
        nullptr, 0, part, 2048, 2048, nullptr, nullptr, 0, nullptr, BATCH * 2048);
    epi_reduce<<<4096, 256>>>(part, 2, 1024, out_b, 0,
                              out, NOUT, NOUT, nullptr, nullptr, 0);
}

// round 16
// speedup vs baseline: 1.0379x; 1.0105x over previous
#include <cuda_runtime.h>
#include <cuda_bf16.h>
#include <cstdint>

#define BATCH    1024
#define TOT      4096
#define SEN      1024
#define CNNOUT   3264
#define KPAD     3328
#define NOUT     1968
#define NOUT_PAD 2048
#define HB       512                         // rows per chain
#define PARTC    ((size_t)4 * HB * 1024)     // split-K partial floats per chain

// ---------------- scratch device globals (no allocations) -------------------
__device__ __align__(256) __nv_bfloat16 g_featH[(size_t)BATCH * KPAD];
__device__ __align__(256) __nv_bfloat16 g_featL[(size_t)BATCH * KPAD];
__device__ __align__(256) __nv_bfloat16 g_ipwH [(size_t)SEN * KPAD];
__device__ __align__(256) __nv_bfloat16 g_ipwL [(size_t)SEN * KPAD];
__device__ __align__(256) __nv_bfloat16 g_WH   [(size_t)TOT * TOT];
__device__ __align__(256) __nv_bfloat16 g_WL   [(size_t)TOT * TOT];
__device__ __align__(256) __nv_bfloat16 g_owH  [(size_t)NOUT_PAD * 1024];
__device__ __align__(256) __nv_bfloat16 g_owL  [(size_t)NOUT_PAD * 1024];
__device__ __align__(256) __nv_bfloat16 g_P0H  [(size_t)BATCH * TOT];
__device__ __align__(256) __nv_bfloat16 g_P0L  [(size_t)BATCH * TOT];
__device__ __align__(256) __nv_bfloat16 g_P1H  [(size_t)BATCH * TOT];
__device__ __align__(256) __nv_bfloat16 g_P1L  [(size_t)BATCH * TOT];
__device__ __align__(256) __nv_bfloat16 g_OPH  [(size_t)BATCH * 1024];
__device__ __align__(256) __nv_bfloat16 g_OPL  [(size_t)BATCH * 1024];
__device__ __align__(256) __nv_bfloat16 g_laH [(size_t)TOT * 64];
__device__ __align__(256) __nv_bfloat16 g_laL [(size_t)TOT * 64];
__device__ __align__(256) __nv_bfloat16 g_lbtH[(size_t)TOT * 64];
__device__ __align__(256) __nv_bfloat16 g_lbtL[(size_t)TOT * 64];
__device__ __align__(256) float g_part[(size_t)2 * PARTC + (size_t)4 * BATCH * 1024 / 2]; // 2 chains + t0 region

// ---------------- helpers ----------------------------------------------------
__device__ __forceinline__ uint32_t smem_u32(const void* p) {
    uint32_t a;
    asm("{ .reg .u64 t; cvta.to.shared.u64 t, %1; cvt.u32.u64 %0, t; }" : "=r"(a) : "l"(p));
    return a;
}
__device__ __forceinline__ void cpa(uint32_t dst, const void* src) {
    asm volatile("cp.async.cg.shared.global [%0], [%1], 16;" :: "r"(dst), "l"(src));
}
#define CP_COMMIT() asm volatile("cp.async.commit_group;")
#define CP_WAIT0()  asm volatile("cp.async.wait_group 0;")
#define CP_WAIT1()  asm volatile("cp.async.wait_group 1;")

__device__ __forceinline__ void ldsm4(uint32_t* r, uint32_t addr) {
    asm volatile("ldmatrix.sync.aligned.m8n8.x4.shared.b16 {%0,%1,%2,%3}, [%4];"
                 : "=r"(r[0]), "=r"(r[1]), "=r"(r[2]), "=r"(r[3]) : "r"(addr));
}
__device__ __forceinline__ void mma16816(float* c, const uint32_t* a, const uint32_t* b) {
    asm volatile("mma.sync.aligned.m16n8k16.row.col.f32.bf16.bf16.f32 "
                 "{%0,%1,%2,%3}, {%4,%5,%6,%7}, {%8,%9}, {%0,%1,%2,%3};"
                 : "+f"(c[0]), "+f"(c[1]), "+f"(c[2]), "+f"(c[3])
                 : "r"(a[0]), "r"(a[1]), "r"(a[2]), "r"(a[3]), "r"(b[0]), "r"(b[1]));
}

__device__ __forceinline__ void split8(const float* v, uint4& uh, uint4& ul) {
    uint32_t h[4], l[4];
#pragma unroll
    for (int q = 0; q < 4; q++) {
        __nv_bfloat16 b0 = __float2bfloat16(v[2 * q]);
        __nv_bfloat16 b1 = __float2bfloat16(v[2 * q + 1]);
        float r0 = v[2 * q]     - __bfloat162float(b0);
        float r1 = v[2 * q + 1] - __bfloat162float(b1);
        __nv_bfloat16 c0 = __float2bfloat16(r0);
        __nv_bfloat16 c1 = __float2bfloat16(r1);
        h[q] = (uint32_t)__bfloat16_as_ushort(b0) | ((uint32_t)__bfloat16_as_ushort(b1) << 16);
        l[q] = (uint32_t)__bfloat16_as_ushort(c0) | ((uint32_t)__bfloat16_as_ushort(c1) << 16);
    }
    uh = make_uint4(h[0], h[1], h[2], h[3]);
    ul = make_uint4(l[0], l[1], l[2], l[3]);
}
__device__ __forceinline__ void pack2(float v0, float v1, uint32_t& ph, uint32_t& pl) {
    __nv_bfloat16 h0 = __float2bfloat16(v0);
    __nv_bfloat16 h1 = __float2bfloat16(v1);
    __nv_bfloat16 q0 = __float2bfloat16(v0 - __bfloat162float(h0));
    __nv_bfloat16 q1 = __float2bfloat16(v1 - __bfloat162float(h1));
    ph = (uint32_t)__bfloat16_as_ushort(h0) | ((uint32_t)__bfloat16_as_ushort(h1) << 16);
    pl = (uint32_t)__bfloat16_as_ushort(q0) | ((uint32_t)__bfloat16_as_ushort(q1) << 16);
}

struct ConvPtrs { const float* w[8]; };

// ---------------- fused: conv feature extraction + ip_w pack ----------------
__global__ __launch_bounds__(256) void fused_prep(
    const float* __restrict__ x, ConvPtrs cw, const float* __restrict__ conv_b,
    __nv_bfloat16* __restrict__ fH, __nv_bfloat16* __restrict__ fL,
    const float* __restrict__ ipw,
    __nv_bfloat16* __restrict__ iH, __nv_bfloat16* __restrict__ iL)
{
    __shared__ float sm[64 * 65];
    const int tid = threadIdx.x;
    const int bid = blockIdx.x;

    if (bid < BATCH) {
        float* xs = sm;
        const float* xb = x + bid * 512;
        for (int i = tid; i < 512; i += 256) xs[i] = xb[i];
        __syncthreads();

        const int offs[9] = {0, 1024, 1808, 2384, 2784, 3040, 3184, 3248, 3264};
        for (int o = tid; o < KPAD; o += 256) {
            if (o >= CNNOUT) {
                fH[(size_t)bid * KPAD + o] = __ushort_as_bfloat16(0);
                fL[(size_t)bid * KPAD + o] = __ushort_as_bfloat16(0);
                continue;
            }
            int k = 1;
            while (o >= offs[k]) k++;
            int local = o - offs[k - 1];
            int H = 9 - k;
            int f = local / (H * H);
            int rem = local - f * H * H;
            int i0 = rem / H;
            int j0 = rem - i0 * H;

            const float* w = cw.w[k - 1] + f * 8 * k * k;
            float acc = conv_b[(k - 1) * 16 + f];
            for (int c = 0; c < 8; c++) {
                const float* wc = w + c * k * k;
                for (int p = 0; p < k; p++)
                    for (int q = 0; q < k; q++)
                        acc += xs[((i0 + p) * 8 + (j0 + q)) * 8 + c] * wc[p * k + q];
            }
            float e = fmaxf(acc, 0.0f);
            __nv_bfloat16 bh = __float2bfloat16(e);
            __nv_bfloat16 bl = __float2bfloat16(e - __bfloat162float(bh));
            fH[(size_t)bid * KPAD + o] = bh;
            fL[(size_t)bid * KPAD + o] = bl;
        }
    } else {
        const int pb = bid - BATCH;
        const int k0 = (pb % (KPAD / 64)) * 64;
        const int n0 = (pb / (KPAD / 64)) * 64;

        for (int i = tid; i < 4096; i += 256) {
            int k = i >> 6, n = i & 63;
            int gn = n0 + n, gk = k0 + k;
            sm[k * 65 + n] = (gn < SEN && gk < CNNOUT) ? ipw[(size_t)gk * SEN + gn] : 0.0f;
        }
        __syncthreads();

        for (int it = tid; it < 512; it += 256) {
            int n = it & 63, kg = it >> 6;
            float v[8];
#pragma unroll
            for (int j = 0; j < 8; j++) v[j] = sm[(kg * 8 + j) * 65 + n];
            uint4 uh, ul;
            split8(v, uh, ul);
            size_t o = (size_t)(n0 + n) * KPAD + k0 + kg * 8;
            *(uint4*)((char*)iH + o * 2) = uh;
            *(uint4*)((char*)iL + o * 2) = ul;
        }
    }
}

// ---------------- pack [K,N] fp32 weight transposed -> [N,K] hi/lo bf16 -----
__global__ __launch_bounds__(256) void pack_wT(const float* __restrict__ w,
                                               int ldw, int ntrue, int ktrue, int ldk,
                                               __nv_bfloat16* __restrict__ H,
                                               __nv_bfloat16* __restrict__ L)
{
    __shared__ float sm[64 * 65];
    const int k0 = blockIdx.x * 64, n0 = blockIdx.y * 64;
    const int tid = threadIdx.x;

    for (int i = tid; i < 4096; i += 256) {
        int k = i >> 6, n = i & 63;
        int gn = n0 + n, gk = k0 + k;
        sm[k * 65 + n] = (gn < ntrue && gk < ktrue) ? w[(size_t)gk * ldw + gn] : 0.0f;
    }
    __syncthreads();

    for (int it = tid; it < 512; it += 256) {
        int n = it & 63, kg = it >> 6;
        float v[8];
#pragma unroll
        for (int j = 0; j < 8; j++) v[j] = sm[(kg * 8 + j) * 65 + n];
        uint4 uh, ul;
        split8(v, uh, ul);
        size_t o = (size_t)(n0 + n) * ldk + k0 + kg * 8;
        *(uint4*)((char*)H + o * 2) = uh;
        *(uint4*)((char*)L + o * 2) = ul;
    }
}

// ---------------- straight split-copy fp32 -> hi/lo bf16 --------------------
__global__ void split_copy(const float* __restrict__ in,
                           __nv_bfloat16* __restrict__ H,
                           __nv_bfloat16* __restrict__ L, int n8)
{
    int i = blockIdx.x * blockDim.x + threadIdx.x;
    if (i >= n8) return;
    float v[8];
    *(float4*)(v)     = *(const float4*)(in + (size_t)i * 8);
    *(float4*)(v + 4) = *(const float4*)(in + (size_t)i * 8 + 4);
    uint4 uh, ul;
    split8(v, uh, ul);
    *(uint4*)((char*)H + (size_t)i * 16) = uh;
    *(uint4*)((char*)L + (size_t)i * 16) = ul;
}

// ---------------- generic split-K reduce epilogue ---------------------------
__global__ __launch_bounds__(256) void epi_reduce(
    const float* __restrict__ part, int nz, int partW2, int rows,
    const float* __restrict__ bias,
    int do_relu,
    float* __restrict__ fOut, int ldO, int ncolO,
    __nv_bfloat16* __restrict__ PH, __nv_bfloat16* __restrict__ PL, int ldP)
{
    const int i = blockIdx.x * blockDim.x + threadIdx.x;
    const int r = i / partW2;
    const int c2 = (i - r * partW2) * 2;
    const int partW = partW2 * 2;
    if (r >= rows) return;
    float v0 = 0.0f, v1 = 0.0f;
    for (int z = 0; z < nz; z++) {
        float2 p = *(const float2*)(part + (size_t)z * rows * partW + (size_t)r * partW + c2);
        v0 += p.x; v1 += p.y;
    }
    if (bias && c2 + 1 < ncolO) {
        float2 b = *(const float2*)(bias + c2);
        v0 += b.x; v1 += b.y;
    }
    if (do_relu) { v0 = fmaxf(v0, 0.0f); v1 = fmaxf(v1, 0.0f); }
    if (fOut && c2 + 1 < ncolO)
        *(float2*)(fOut + (size_t)r * ldO + c2) = make_float2(v0, v1);
    if (PH) {
        uint32_t ph, pl;
        pack2(v0, v1, ph, pl);
        *(uint32_t*)((char*)PH + ((size_t)r * ldP + c2) * 2) = ph;
        *(uint32_t*)((char*)PL + ((size_t)r * ldP + c2) * 2) = pl;
    }
}

// ---------------- mma.sync bf16-split GEMM ----------------------------------
// 256 threads, 2 CTAs/SM. Tile 128x128, warp tile 64x32. KCH=32, 3 stages.
// One barrier per chunk; B fragments for both kk-slices prefetched; next
// chunk's cp.async issued between slices. Residual folded into W (W'=W_eff+I).
// 3-term bf16 split. z = split-K slice. MSWAP swaps block x/y. WEFF epilogue.
template<int STAGES, int KCH, bool WEFF, bool MSWAP>
__global__ __launch_bounds__(256, 2)
void mma_gemm(const __nv_bfloat16* __restrict__ AH, const __nv_bfloat16* __restrict__ AL, int lda,
              const __nv_bfloat16* __restrict__ BH, const __nv_bfloat16* __restrict__ BL, int ldb,
              int K,
              const float* __restrict__ bias, int do_relu,
              float* __restrict__ outF, int ldF, int ncolF,
              __nv_bfloat16* __restrict__ PH, __nv_bfloat16* __restrict__ PL, int ldP,
              const float* __restrict__ Wsrc, int partStride)
{
    static_assert(KCH == 32, "chunk layout assumes KCH==32 (2 kk-slices)");
    constexpr int GPC   = KCH / 8;
    constexpr int AHALF = 128 * KCH * 2;
    constexpr int STG   = 4 * AHALF;
    extern __shared__ __align__(128) char smc[];

    const int tid = threadIdx.x, l = tid & 31, wid = tid >> 5;
    const int nblk = MSWAP ? blockIdx.y : blockIdx.x;
    const int mblk = MSWAP ? blockIdx.x : blockIdx.y;
    const int zo = blockIdx.z;
    const int KB = K / KCH;
    const uint32_t smb = smem_u32(smc);
    const int mrow0 = mblk * 128;
    const int nrow0 = nblk * 128;

    AH += (size_t)zo * K; AL += (size_t)zo * K;
    BH += (size_t)zo * K; BL += (size_t)zo * K;
    if (outF) outF += (size_t)zo * partStride;

    auto swof = [](int r, uint32_t g) -> uint32_t {
        return (uint32_t)r * 64 + ((g ^ (uint32_t)((r >> 1) & 3)) << 4);
    };

    auto load_chunk = [&](int s, int c) {
        const int kof = c * KCH;
        const uint32_t sb = smb + (uint32_t)s * STG;
#pragma unroll
        for (int it = 0; it < (4 * 128 * GPC) / 256; it++) {
            int idx = tid + it * 256;
            int mat = idx / (128 * GPC);
            int j = idx - mat * (128 * GPC);
            int r = j / GPC, g = j - r * GPC;
            const __nv_bfloat16* src =
                (mat == 0 ? AH : mat == 1 ? AL : mat == 2 ? BH : BL);
            const int row0 = (mat < 2) ? mrow0 : nrow0;
            const int ld   = (mat < 2) ? lda : ldb;
            cpa(sb + (uint32_t)mat * AHALF + swof(r, (uint32_t)g),
                src + (size_t)(row0 + r) * ld + kof + g * 8);
        }
    };

    const int mw = wid & 1, nw = wid >> 1;
    const int mbase = mw * 64, nbase = nw * 32;
    const int rA0 = mbase + (l & 7) + ((l >> 3) & 1) * 8;
    const int rB0 = nbase + (l & 7) + ((l >> 3) & 1) * 8;
    const int gsel = l >> 4;

    float acc[4][4][4];
#pragma unroll
    for (int a = 0; a < 4; a++)
#pragma unroll
        for (int b = 0; b < 4; b++)
#pragma unroll
            for (int c = 0; c < 4; c++) acc[a][b][c] = 0.0f;

    auto prefetch_B = [&](uint32_t base, int kk, uint32_t bh[4][2], uint32_t bl[4][2]) {
        const uint32_t g = 2 * kk + gsel;
#pragma unroll
        for (int p = 0; p < 2; p++) {
            uint32_t t0[4], t1[4];
            uint32_t addr = base + 2 * AHALF + swof(rB0 + p * 16, g);
            ldsm4(t0, addr);
            ldsm4(t1, addr + AHALF);
            bh[2 * p][0] = t0[0]; bh[2 * p][1] = t0[2];
            bh[2 * p + 1][0] = t0[1]; bh[2 * p + 1][1] = t0[3];
            bl[2 * p][0] = t1[0]; bl[2 * p][1] = t1[2];
            bl[2 * p + 1][0] = t1[1]; bl[2 * p + 1][1] = t1[3];
        }
    };

    auto mma_slice = [&](uint32_t base, int kk, uint32_t bh[4][2], uint32_t bl[4][2]) {
        const uint32_t g = 2 * kk + gsel;
#pragma unroll
        for (int mt = 0; mt < 4; mt++) {
            uint32_t ah[4], al_[4];
            uint32_t addr = base + swof(rA0 + mt * 16, g);
            ldsm4(ah, addr);
            ldsm4(al_, addr + AHALF);
#pragma unroll
            for (int nt = 0; nt < 4; nt++) mma16816(acc[mt][nt], ah, bh[nt]);
#pragma unroll
            for (int nt = 0; nt < 4; nt++) mma16816(acc[mt][nt], ah, bl[nt]);
#pragma unroll
            for (int nt = 0; nt < 4; nt++) mma16816(acc[mt][nt], al_, bh[nt]);
        }
    };

#pragma unroll
    for (int s = 0; s < STAGES - 1; s++) {
        if (s < KB) load_chunk(s, s);
        CP_COMMIT();
    }
    for (int c = 0; c < KB; c++) {
        const int s = c % STAGES;
        if (STAGES == 3) { CP_WAIT1(); } else { CP_WAIT0(); }
        __syncthreads();
        const uint32_t base = smb + (uint32_t)s * STG;

        uint32_t b0h[4][2], b0l[4][2], b1h[4][2], b1l[4][2];
        prefetch_B(base, 0, b0h, b0l);
        prefetch_B(base, 1, b1h, b1l);
        mma_slice(base, 0, b0h, b0l);
        if (c + STAGES - 1 < KB) load_chunk((c + STAGES - 1) % STAGES, c + STAGES - 1);
        CP_COMMIT();
        mma_slice(base, 1, b1h, b1l);
    }

    const int rr = l >> 2, cc = (l & 3) * 2;

    if (WEFF) {
        __syncthreads();
        float* Wt = (float*)smc;
        for (int i = tid; i < 128 * 128; i += 256) {
            int kk = i >> 7, n = i & 127;
            Wt[n * 129 + kk] = Wsrc[(size_t)(nrow0 + kk) * TOT + mrow0 + n];
        }
        __syncthreads();
#pragma unroll
        for (int mt = 0; mt < 4; mt++)
#pragma unroll
            for (int h = 0; h < 2; h++) {
                const int rl = mbase + mt * 16 + rr + h * 8;
                const int rg = mrow0 + rl;
                const size_t r = (size_t)rg;
#pragma unroll
                for (int nt = 0; nt < 4; nt++) {
                    const int cl = nbase + nt * 8 + cc;
                    const int cx = nrow0 + cl;
                    float w0 = Wt[rl * 129 + cl];
                    float w1 = Wt[rl * 129 + cl + 1];
                    float v0 = (w0 == 0.0f) ? 0.0f : (w0 + 2.0f * acc[mt][nt][h * 2 + 0]);
                    float v1 = (w1 == 0.0f) ? 0.0f : (w1 + 2.0f * acc[mt][nt][h * 2 + 1]);
                    if (rg == cx)     v0 += 1.0f;
                    if (rg == cx + 1) v1 += 1.0f;
                    uint32_t ph, pl;
                    pack2(v0, v1, ph, pl);
                    *(uint32_t*)((char*)PH + (r * ldP + cx) * 2) = ph;
                    *(uint32_t*)((char*)PL + (r * ldP + cx) * 2) = pl;
                }
            }
        return;
    }

    const int growb = mrow0 + mbase;
    const int gcolb = nrow0 + nbase;
#pragma unroll
    for (int mt = 0; mt < 4; mt++)
#pragma unroll
        for (int h = 0; h < 2; h++) {
            const int r = growb + mt * 16 + rr + h * 8;
#pragma unroll
            for (int nt = 0; nt < 4; nt++) {
                const int cx = gcolb + nt * 8 + cc;
                float v0 = acc[mt][nt][h * 2 + 0];
                float v1 = acc[mt][nt][h * 2 + 1];
                if (bias && cx < ncolF) {
                    float2 bv = *(const float2*)(bias + cx);
                    v0 += bv.x; v1 += bv.y;
                }
                if (do_relu) { v0 = fmaxf(v0, 0.0f); v1 = fmaxf(v1, 0.0f); }
                if (outF && cx < ncolF)
                    *(float2*)(outF + (size_t)r * ldF + cx) = make_float2(v0, v1);
                if (PH) {
                    uint32_t ph, pl;
                    pack2(v0, v1, ph, pl);
                    *(uint32_t*)((char*)PH + ((size_t)r * ldP + cx) * 2) = ph;
                    *(uint32_t*)((char*)PL + ((size_t)r * ldP + cx) * 2) = pl;
                }
            }
        }
}

// ---------------- launch ----------------------------------------------------
extern "C" void kernel_launch(void* const* d_in, const int* in_sizes, int n_in,
                              void* d_out, int out_size)
{
    const float* x      = (const float*)d_in[0];
    ConvPtrs cw;
    for (int i = 0; i < 8; i++) cw.w[i] = (const float*)d_in[1 + i];
    const float* conv_b = (const float*)d_in[9];
    const float* W      = (const float*)d_in[10];
    const float* lora_A = (const float*)d_in[11];
    const float* lora_B = (const float*)d_in[12];
    const float* ip_w   = (const float*)d_in[13];
    const float* ip_b   = (const float*)d_in[14];
    const float* out_w  = (const float*)d_in[15];
    const float* out_b  = (const float*)d_in[16];
    float* out = (float*)d_out;

    __nv_bfloat16 *featH, *featL, *ipwH, *ipwL, *WH, *WL, *owH, *owL;
    __nv_bfloat16 *P0H, *P0L, *P1H, *P1L, *OPH, *OPL, *laH, *laL, *lbtH, *lbtL;
    float* part;
    cudaGetSymbolAddress((void**)&featH, g_featH);
    cudaGetSymbolAddress((void**)&featL, g_featL);
    cudaGetSymbolAddress((void**)&ipwH,  g_ipwH);
    cudaGetSymbolAddress((void**)&ipwL,  g_ipwL);
    cudaGetSymbolAddress((void**)&WH,    g_WH);
    cudaGetSymbolAddress((void**)&WL,    g_WL);
    cudaGetSymbolAddress((void**)&owH,   g_owH);
    cudaGetSymbolAddress((void**)&owL,   g_owL);
    cudaGetSymbolAddress((void**)&P0H,   g_P0H);
    cudaGetSymbolAddress((void**)&P0L,   g_P0L);
    cudaGetSymbolAddress((void**)&P1H,   g_P1H);
    cudaGetSymbolAddress((void**)&P1L,   g_P1L);
    cudaGetSymbolAddress((void**)&OPH,   g_OPH);
    cudaGetSymbolAddress((void**)&OPL,   g_OPL);
    cudaGetSymbolAddress((void**)&laH,   g_laH);
    cudaGetSymbolAddress((void**)&laL,   g_laL);
    cudaGetSymbolAddress((void**)&lbtH,  g_lbtH);
    cudaGetSymbolAddress((void**)&lbtL,  g_lbtL);
    cudaGetSymbolAddress((void**)&part,  g_part);

    const int SMEM = 3 * 4 * 128 * 32 * 2;   // 98304
    cudaFuncSetAttribute(mma_gemm<3, 32, false, false>, cudaFuncAttributeMaxDynamicSharedMemorySize, SMEM);
    cudaFuncSetAttribute(mma_gemm<3, 32, false, true>,  cudaFuncAttributeMaxDynamicSharedMemorySize, SMEM);
    cudaFuncSetAttribute(mma_gemm<3, 32, true, false>,  cudaFuncAttributeMaxDynamicSharedMemorySize, SMEM);

    // streams/events: created once on first call (pre-baseline), reused.
    static cudaStream_t s1 = nullptr, s2 = nullptr;
    static cudaEvent_t eF1 = nullptr, eF2 = nullptr, eJ1 = nullptr, eJ2 = nullptr;
    static cudaEvent_t eC = nullptr, eJ3 = nullptr;
    if (s1 == nullptr) {
        cudaStreamCreateWithFlags(&s1, cudaStreamNonBlocking);
        cudaStreamCreateWithFlags(&s2, cudaStreamNonBlocking);
        cudaEventCreateWithFlags(&eF1, cudaEventDisableTiming);
        cudaEventCreateWithFlags(&eF2, cudaEventDisableTiming);
        cudaEventCreateWithFlags(&eJ1, cudaEventDisableTiming);
        cudaEventCreateWithFlags(&eJ2, cudaEventDisableTiming);
        cudaEventCreateWithFlags(&eC,  cudaEventDisableTiming);
        cudaEventCreateWithFlags(&eJ3, cudaEventDisableTiming);
    }

    // fork prologue
    cudaEventRecord(eF1, 0);
    cudaEventRecord(eF2, 0);
    cudaStreamWaitEvent(s1, eF1, 0);
    cudaStreamWaitEvent(s2, eF2, 0);

    // stream0: fused(conv + ip_w pack) -> t0 -> epi0
    fused_prep<<<BATCH + (KPAD / 64) * (SEN / 64), 256>>>(
        x, cw, conv_b, featH, featL, ip_w, ipwH, ipwL);
    mma_gemm<3, 32, false, false><<<dim3(SEN / 128, 8, 4), 256, SMEM>>>(
        featH, featL, KPAD, ipwH, ipwL, KPAD, 832,
        nullptr, 0, part, 1024, 1024, nullptr, nullptr, 0, nullptr, BATCH * 1024);
    epi_reduce<<<2048, 256>>>(part, 4, 512, BATCH, ip_b, 1,
                              nullptr, 0, 1024, P0H, P0L, TOT);

    // s1: lora packs + W' = W_eff + I
    split_copy<<<(TOT * 64 / 8 + 255) / 256, 256, 0, s1>>>(lora_A, laH, laL, TOT * 64 / 8);
    pack_wT<<<dim3(1, TOT / 64), 256, 0, s1>>>(lora_B, TOT, TOT, 64, 64, lbtH, lbtL);
    mma_gemm<3, 32, true, false><<<dim3(32, 32), 256, SMEM, s1>>>(
        lbtH, lbtL, 64, laH, laL, 64, 64,
        nullptr, 0, nullptr, 0, 0, WH, WL, TOT, W, 0);

    // s2: out_w pack
    pack_wT<<<dim3(1024 / 64, NOUT_PAD / 64), 256, 0, s2>>>(out_w, NOUT, NOUT, 1024, 1024, owH, owL);

    // join all prep into stream0, then fork two batch-half chains
    cudaEventRecord(eJ1, s1);
    cudaEventRecord(eJ2, s2);
    cudaStreamWaitEvent(0, eJ1, 0);
    cudaStreamWaitEvent(0, eJ2, 0);
    cudaEventRecord(eC, 0);
    cudaStreamWaitEvent(s1, eC, 0);

    // chain c on stream (c==0 ? stream0 : s1), rows [c*HB, (c+1)*HB)
    for (int c = 0; c < 2; c++) {
        cudaStream_t st = (c == 0) ? (cudaStream_t)0 : s1;
        const size_t ro = (size_t)c * HB;
        float* pc = part + (size_t)c * PARTC;

        // t1 (K = 1024)
        mma_gemm<3, 32, false, true><<<dim3(HB / 128, TOT / 128), 256, SMEM, st>>>(
            P0H + ro * TOT, P0L + ro * TOT, TOT, WH, WL, TOT, 1024,
            nullptr, 1, nullptr, 0, 0, P1H + ro * TOT, P1L + ro * TOT, TOT, nullptr, 0);
        // t2
        mma_gemm<3, 32, false, true><<<dim3(HB / 128, TOT / 128), 256, SMEM, st>>>(
            P1H + ro * TOT, P1L + ro * TOT, TOT, WH, WL, TOT, TOT,
            nullptr, 1, nullptr, 0, 0, P0H + ro * TOT, P0L + ro * TOT, TOT, nullptr, 0);
        // t3
        mma_gemm<3, 32, false, true><<<dim3(HB / 128, TOT / 128), 256, SMEM, st>>>(
            P0H + ro * TOT, P0L + ro * TOT, TOT, WH, WL, TOT, TOT,
            nullptr, 1, nullptr, 0, 0, P1H + ro * TOT, P1L + ro * TOT, TOT, nullptr, 0);

        // t4: split-K=4 -> partials (slices of HB x 1024)
        mma_gemm<3, 32, false, false><<<dim3(8, HB / 128, 4), 256, SMEM, st>>>(
            P1H + ro * TOT, P1L + ro * TOT, TOT,
            WH + (size_t)3072 * TOT, WL + (size_t)3072 * TOT, TOT, 1024,
            nullptr, 0, pc, 1024, 1024, nullptr, nullptr, 0, nullptr, HB * 1024);
        epi_reduce<<<HB * 512 / 256, 256, 0, st>>>(pc, 4, 512, HB, nullptr, 1,
                                                   nullptr, 0, 1024, OPH + ro * 1024, OPL + ro * 1024, 1024);

        // out GEMM split-K=2 -> partials (slices HB x 2048) -> reduce+bias
        mma_gemm<3, 32, false, false><<<dim3(NOUT_PAD / 128, HB / 128, 2), 256, SMEM, st>>>(
            OPH + ro * 1024, OPL + ro * 1024, 1024, owH, owL, 1024, 512,
            nullptr, 0, pc, 2048, 2048, nullptr, nullptr, 0, nullptr, HB * 2048);
        epi_reduce<<<HB * 1024 / 256, 256, 0, st>>>(pc, 2, 1024, HB, out_b, 0,
                                                    out + ro * NOUT, NOUT, NOUT, nullptr, nullptr, 0);
    }

    // join chain1 back into stream0
    cudaEventRecord(eJ3, s1);
    cudaStreamWaitEvent(0, eJ3, 0);
}